// round 10
// baseline (speedup 1.0000x reference)
#include <cuda_runtime.h>
#include <cuda_fp16.h>
#include <math.h>
#include <stdint.h>

#define N_NODES 50000
#define N_EDGES 800000
#define NEG_SLOPE 0.2f

// ---------------- scratch (device globals; no allocation allowed) ----------------
__device__ float  g_ft1[N_NODES * 256];
__device__ float  g_h1 [N_NODES * 256];
__device__ float  g_el1[N_NODES * 4];
__device__ float  g_er1[N_NODES * 4];
__device__ float  g_ft2[N_NODES * 128];
__device__ float  g_el2p[2 * N_NODES];
__device__ float  g_er2p[2 * N_NODES];
__device__ int    g_cnt[N_NODES];
__device__ int    g_rowptr[N_NODES + 1];
__device__ int    g_colsrc[N_EDGES];
__device__ __half g_wt1h[256 * 256];   // W1^T hi fp16 [n][k]
__device__ __half g_wt1l[256 * 256];   // W1^T lo fp16
__device__ __half g_wt2h[128 * 256];   // W2^T hi
__device__ __half g_wt2l[128 * 256];   // W2^T lo

// ---------------- helpers ----------------
__device__ __forceinline__ uint32_t smem_u32(const void* p) {
    uint32_t a;
    asm("{ .reg .u64 t; cvta.to.shared.u64 t, %1; cvt.u32.u64 %0, t; }" : "=r"(a) : "l"(p));
    return a;
}

#define CP_ASYNC16(sa, gp) \
    asm volatile("cp.async.cg.shared.global [%0], [%1], 16;" :: "r"(sa), "l"(gp) : "memory")
#define CP_ASYNC16_Z(sa, gp, sz) \
    asm volatile("cp.async.cg.shared.global [%0], [%1], 16, %2;" :: "r"(sa), "l"(gp), "r"(sz) : "memory")
#define CP_COMMIT()  asm volatile("cp.async.commit_group;" ::: "memory")
#define CP_WAIT(n)   asm volatile("cp.async.wait_group %0;" :: "n"(n) : "memory")

#define MMA_F16(d, a0, a1, a2, a3, b0, b1)                                    \
    asm volatile("mma.sync.aligned.m16n8k16.row.col.f32.f16.f16.f32 "         \
                 "{%0,%1,%2,%3}, {%4,%5,%6,%7}, {%8,%9}, {%0,%1,%2,%3};"      \
                 : "+f"(d[0]), "+f"(d[1]), "+f"(d[2]), "+f"(d[3])             \
                 : "r"(a0), "r"(a1), "r"(a2), "r"(a3), "r"(b0), "r"(b1))

// split a float2 into packed fp16 hi + fp16 residual lo
__device__ __forceinline__ void split2(float2 x, uint32_t& h, uint32_t& l) {
    __half2 hh = __floats2half2_rn(x.x, x.y);
    float2 hf = __half22float2(hh);
    __half2 ll = __floats2half2_rn(x.x - hf.x, x.y - hf.y);
    h = *reinterpret_cast<uint32_t*>(&hh);
    l = *reinterpret_cast<uint32_t*>(&ll);
}

// ---------------- small utils ----------------
__global__ void zero_int_kernel(int* __restrict__ p, int n) {
    for (int i = blockIdx.x * blockDim.x + threadIdx.x; i < n; i += gridDim.x * blockDim.x)
        p[i] = 0;
}

__global__ void count_dst_kernel(const int* __restrict__ dst, int* __restrict__ cnt, int E) {
    for (int e = blockIdx.x * blockDim.x + threadIdx.x; e < E; e += gridDim.x * blockDim.x)
        atomicAdd(&cnt[dst[e]], 1);
}

// transpose + fp16 hi/lo split of both weight matrices
__global__ void transpose_split_kernel(const float* __restrict__ W1, const float* __restrict__ W2,
                                       __half* __restrict__ t1h, __half* __restrict__ t1l,
                                       __half* __restrict__ t2h, __half* __restrict__ t2l) {
    int t = blockIdx.x * blockDim.x + threadIdx.x;
    if (t < 65536) {
        int k = t & 255, n = t >> 8;
        float v = W1[k * 256 + n];
        __half h = __float2half_rn(v);
        t1h[n * 256 + k] = h;
        t1l[n * 256 + k] = __float2half_rn(v - __half2float(h));
    } else if (t < 98304) {
        int u = t - 65536;
        int k = u & 255, n = u >> 8;
        float v = W2[k * 128 + n];
        __half h = __float2half_rn(v);
        t2h[n * 256 + k] = h;
        t2l[n * 256 + k] = __float2half_rn(v - __half2float(h));
    }
}

// single-block exclusive scan
__global__ void scan_kernel(const int* __restrict__ cnt, int* __restrict__ rowptr, int n) {
    __shared__ int warp_sums[32];
    __shared__ int s_carry;
    int tid = threadIdx.x;
    if (tid == 0) { s_carry = 0; rowptr[0] = 0; }
    __syncthreads();
    for (int base = 0; base < n; base += 1024) {
        int idx = base + tid;
        int v = (idx < n) ? cnt[idx] : 0;
        int lane = tid & 31, warp = tid >> 5;
        int x = v;
        #pragma unroll
        for (int off = 1; off < 32; off <<= 1) {
            int y = __shfl_up_sync(0xffffffffu, x, off);
            if (lane >= off) x += y;
        }
        if (lane == 31) warp_sums[warp] = x;
        __syncthreads();
        if (warp == 0) {
            int s = warp_sums[lane];
            #pragma unroll
            for (int off = 1; off < 32; off <<= 1) {
                int y = __shfl_up_sync(0xffffffffu, s, off);
                if (lane >= off) s += y;
            }
            warp_sums[lane] = s;
        }
        __syncthreads();
        int warp_off = (warp > 0) ? warp_sums[warp - 1] : 0;
        int incl = x + warp_off + s_carry;
        if (idx < n) rowptr[idx + 1] = incl;
        __syncthreads();
        if (tid == 1023) s_carry = incl;
        __syncthreads();
    }
}

__global__ void scatter_kernel(const int* __restrict__ src, const int* __restrict__ dst,
                               const int* __restrict__ rowptr, int* __restrict__ cnt,
                               int* __restrict__ colsrc, int E) {
    for (int e = blockIdx.x * blockDim.x + threadIdx.x; e < E; e += gridDim.x * blockDim.x) {
        int d = dst[e];
        int pos = atomicSub(&cnt[d], 1);
        colsrc[rowptr[d] + pos - 1] = src[e];
    }
}

// ---------------- fp16 split-MMA GEMM (cp.async double-buffered) + fused el/er ----------------
template <int HEADS>
__global__ __launch_bounds__(256, 3) void mma_gemm_f16_kernel(
    const float* __restrict__ A,
    const __half* __restrict__ Bth, const __half* __restrict__ Btl,
    float* __restrict__ C,
    const float* __restrict__ attn_l, const float* __restrict__ attn_r,
    float* __restrict__ el, float* __restrict__ er,
    int M, int Nc)
{
    const int BM = 128, BN = 64, BK = 32, K = 256;
    const int ASTR = 40;    // f32 per A row
    const int BSTR2 = 20;   // half2 per B row
    extern __shared__ float sm[];
    float*   As  = sm;                                    // [2][BM][40] f32
    __half2* Bh2 = (__half2*)(As + 2 * BM * ASTR);        // [2][BN][20] half2 hi
    __half2* Bl2 = Bh2 + 2 * BN * BSTR2;                  // [2][BN][20] half2 lo
    float*   s_el = (float*)(Bl2 + 2 * BN * BSTR2);       // [BM]
    float*   s_er = s_el + BM;                            // [BM]

    uint32_t as_b = smem_u32(As);
    uint32_t bh_b = smem_u32(Bh2);
    uint32_t bl_b = smem_u32(Bl2);

    int tid = threadIdx.x, lane = tid & 31, warp = tid >> 5;
    int wm = warp >> 1, wn = warp & 1;
    int blockRow = blockIdx.y * BM;
    int blockCol = blockIdx.x * BN;
    int g = lane >> 2, q = lane & 3;

    float acc[2][4][4];
    #pragma unroll
    for (int i = 0; i < 2; i++)
        #pragma unroll
        for (int j = 0; j < 4; j++)
            #pragma unroll
            for (int c = 0; c < 4; c++) acc[i][j][c] = 0.f;

    auto load_tile = [&](int t) {
        int buf = t & 1, k0 = t * BK;
        #pragma unroll
        for (int l = 0; l < 4; l++) {
            int c = tid + l * 256;
            int r = c >> 3, kq = (c & 7) * 4;
            const float* gp = A + (size_t)(blockRow + r) * K + k0 + kq;
            uint32_t sa = as_b + (uint32_t)(((buf * BM + r) * ASTR + kq) * 4);
            uint32_t sz = (blockRow + r < M) ? 16u : 0u;
            CP_ASYNC16_Z(sa, gp, sz);
        }
        {
            int n = tid >> 2, ch = tid & 3;
            size_t go = (size_t)(blockCol + n) * K + k0 + ch * 8;
            uint32_t so = (uint32_t)(((buf * BN + n) * BSTR2 + ch * 4) * 4);
            CP_ASYNC16(bh_b + so, Bth + go);
            CP_ASYNC16(bl_b + so, Btl + go);
        }
        CP_COMMIT();
    };

    load_tile(0);

    #pragma unroll 1
    for (int t = 0; t < K / BK; t++) {
        if (t < K / BK - 1) {
            load_tile(t + 1);
            CP_WAIT(1);
        } else {
            CP_WAIT(0);
        }
        __syncthreads();

        int buf = t & 1;
        const float2*  Af2 = (const float2*)(As + buf * BM * ASTR);
        const __half2* Bhb = Bh2 + buf * BN * BSTR2;
        const __half2* Blb = Bl2 + buf * BN * BSTR2;

        #pragma unroll
        for (int ks = 0; ks < 2; ks++) {
            int kof = ks * 8;
            uint32_t ah[2][4], al[2][4];
            #pragma unroll
            for (int i = 0; i < 2; i++) {
                int r0 = wm * 32 + i * 16 + g;
                float2 x00 = Af2[(r0    ) * 20 + kof + q];
                float2 x10 = Af2[(r0 + 8) * 20 + kof + q];
                float2 x01 = Af2[(r0    ) * 20 + kof + q + 4];
                float2 x11 = Af2[(r0 + 8) * 20 + kof + q + 4];
                split2(x00, ah[i][0], al[i][0]);
                split2(x10, ah[i][1], al[i][1]);
                split2(x01, ah[i][2], al[i][2]);
                split2(x11, ah[i][3], al[i][3]);
            }
            uint32_t bh_[4][2], bl_[4][2];
            #pragma unroll
            for (int j = 0; j < 4; j++) {
                int nb = wn * 32 + j * 8 + g;
                bh_[j][0] = *reinterpret_cast<const uint32_t*>(&Bhb[nb * BSTR2 + kof + q]);
                bh_[j][1] = *reinterpret_cast<const uint32_t*>(&Bhb[nb * BSTR2 + kof + q + 4]);
                bl_[j][0] = *reinterpret_cast<const uint32_t*>(&Blb[nb * BSTR2 + kof + q]);
                bl_[j][1] = *reinterpret_cast<const uint32_t*>(&Blb[nb * BSTR2 + kof + q + 4]);
            }
            #pragma unroll
            for (int i = 0; i < 2; i++)
                #pragma unroll
                for (int j = 0; j < 4; j++) {
                    MMA_F16(acc[i][j], ah[i][0], ah[i][1], ah[i][2], ah[i][3], bh_[j][0], bh_[j][1]);
                    MMA_F16(acc[i][j], al[i][0], al[i][1], al[i][2], al[i][3], bh_[j][0], bh_[j][1]);
                    MMA_F16(acc[i][j], ah[i][0], ah[i][1], ah[i][2], ah[i][3], bl_[j][0], bl_[j][1]);
                }
        }
        __syncthreads();
    }

    // ---- store C (fp32) ----
    #pragma unroll
    for (int i = 0; i < 2; i++) {
        int r0 = blockRow + wm * 32 + i * 16 + g;
        int r1 = r0 + 8;
        #pragma unroll
        for (int j = 0; j < 4; j++) {
            int c = blockCol + wn * 32 + j * 8 + q * 2;
            if (r0 < M) *(float2*)(C + (size_t)r0 * Nc + c) = make_float2(acc[i][j][0], acc[i][j][1]);
            if (r1 < M) *(float2*)(C + (size_t)r1 * Nc + c) = make_float2(acc[i][j][2], acc[i][j][3]);
        }
    }

    // ---- fused el/er epilogue (fp32 accumulators) ----
    float pl[2][2] = {{0.f, 0.f}, {0.f, 0.f}};
    float pr[2][2] = {{0.f, 0.f}, {0.f, 0.f}};
    #pragma unroll
    for (int j = 0; j < 4; j++) {
        int idx = blockCol + wn * 32 + j * 8 + q * 2;
        float a0 = __ldg(&attn_l[idx]), a1 = __ldg(&attn_l[idx + 1]);
        float b0 = __ldg(&attn_r[idx]), b1 = __ldg(&attn_r[idx + 1]);
        #pragma unroll
        for (int i = 0; i < 2; i++) {
            pl[i][0] += acc[i][j][0] * a0 + acc[i][j][1] * a1;
            pl[i][1] += acc[i][j][2] * a0 + acc[i][j][3] * a1;
            pr[i][0] += acc[i][j][0] * b0 + acc[i][j][1] * b1;
            pr[i][1] += acc[i][j][2] * b0 + acc[i][j][3] * b1;
        }
    }
    #pragma unroll
    for (int off = 1; off <= 2; off <<= 1) {
        #pragma unroll
        for (int i = 0; i < 2; i++) {
            pl[i][0] += __shfl_xor_sync(0xffffffffu, pl[i][0], off);
            pl[i][1] += __shfl_xor_sync(0xffffffffu, pl[i][1], off);
            pr[i][0] += __shfl_xor_sync(0xffffffffu, pr[i][0], off);
            pr[i][1] += __shfl_xor_sync(0xffffffffu, pr[i][1], off);
        }
    }
    if (wn == 0 && q == 0) {
        #pragma unroll
        for (int i = 0; i < 2; i++) {
            int row = wm * 32 + i * 16 + g;
            s_el[row]     = pl[i][0];  s_el[row + 8] = pl[i][1];
            s_er[row]     = pr[i][0];  s_er[row + 8] = pr[i][1];
        }
    }
    __syncthreads();
    if (wn == 1 && q == 0) {
        #pragma unroll
        for (int i = 0; i < 2; i++) {
            #pragma unroll
            for (int h8 = 0; h8 < 2; h8++) {
                int row = wm * 32 + i * 16 + g + h8 * 8;
                int r = blockRow + row;
                if (r < M) {
                    float vl = pl[i][h8] + s_el[row];
                    float vr = pr[i][h8] + s_er[row];
                    if (HEADS == 1) {
                        el[(size_t)blockIdx.x * M + r] = vl;
                        er[(size_t)blockIdx.x * M + r] = vr;
                    } else {
                        el[(size_t)r * HEADS + blockIdx.x] = vl;
                        er[(size_t)r * HEADS + blockIdx.x] = vr;
                    }
                }
            }
        }
    }
}

// ---------------- fused softmax + aggregation ----------------
__device__ __forceinline__ float leaky_exp(float e) {
    e = (e > 0.f) ? e : NEG_SLOPE * e;
    return __expf(e);
}

// layer 1: H=4, D=64, C=256, fp32 features. One warp per node.
__global__ __launch_bounds__(256) void aggregate1_kernel(
    const float* __restrict__ ft, const float* __restrict__ el, const float* __restrict__ er,
    const int* __restrict__ rowptr, const int* __restrict__ colsrc,
    const float* __restrict__ bias, float* __restrict__ out, int Nn)
{
    int warp = threadIdx.x >> 5, lane = threadIdx.x & 31;
    int n = blockIdx.x * 8 + warp;
    if (n >= Nn) return;
    int start = rowptr[n];
    int deg = rowptr[n + 1] - start;

    const bool hlo = (lane < 16);
    float4 er4 = __ldg((const float4*)(er + (size_t)n * 4));
    float erA = hlo ? er4.x : er4.y;
    float erB = hlo ? er4.z : er4.w;

    float4 accA = make_float4(0.f, 0.f, 0.f, 0.f);
    float4 accB = make_float4(0.f, 0.f, 0.f, 0.f);
    float wsumA = 0.f, wsumB = 0.f;
    const float* ftA = ft + lane * 4;
    const float* ftB = ft + 128 + lane * 4;

    int k = 0;
    for (; k + 4 <= deg; k += 4) {
        int s0 = __ldg(&colsrc[start + k + 0]);
        int s1 = __ldg(&colsrc[start + k + 1]);
        int s2 = __ldg(&colsrc[start + k + 2]);
        int s3 = __ldg(&colsrc[start + k + 3]);
        float4 l0 = __ldg((const float4*)(el + (size_t)s0 * 4));
        float4 l1 = __ldg((const float4*)(el + (size_t)s1 * 4));
        float4 l2 = __ldg((const float4*)(el + (size_t)s2 * 4));
        float4 l3 = __ldg((const float4*)(el + (size_t)s3 * 4));
        float4 fA0 = *(const float4*)(ftA + (size_t)s0 * 256);
        float4 fB0 = *(const float4*)(ftB + (size_t)s0 * 256);
        float4 fA1 = *(const float4*)(ftA + (size_t)s1 * 256);
        float4 fB1 = *(const float4*)(ftB + (size_t)s1 * 256);
        float4 fA2 = *(const float4*)(ftA + (size_t)s2 * 256);
        float4 fB2 = *(const float4*)(ftB + (size_t)s2 * 256);
        float4 fA3 = *(const float4*)(ftA + (size_t)s3 * 256);
        float4 fB3 = *(const float4*)(ftB + (size_t)s3 * 256);
        float wA0 = leaky_exp((hlo ? l0.x : l0.y) + erA);
        float wB0 = leaky_exp((hlo ? l0.z : l0.w) + erB);
        float wA1 = leaky_exp((hlo ? l1.x : l1.y) + erA);
        float wB1 = leaky_exp((hlo ? l1.z : l1.w) + erB);
        float wA2 = leaky_exp((hlo ? l2.x : l2.y) + erA);
        float wB2 = leaky_exp((hlo ? l2.z : l2.w) + erB);
        float wA3 = leaky_exp((hlo ? l3.x : l3.y) + erA);
        float wB3 = leaky_exp((hlo ? l3.z : l3.w) + erB);
        accA.x += wA0 * fA0.x + wA1 * fA1.x + wA2 * fA2.x + wA3 * fA3.x;
        accA.y += wA0 * fA0.y + wA1 * fA1.y + wA2 * fA2.y + wA3 * fA3.y;
        accA.z += wA0 * fA0.z + wA1 * fA1.z + wA2 * fA2.z + wA3 * fA3.z;
        accA.w += wA0 * fA0.w + wA1 * fA1.w + wA2 * fA2.w + wA3 * fA3.w;
        accB.x += wB0 * fB0.x + wB1 * fB1.x + wB2 * fB2.x + wB3 * fB3.x;
        accB.y += wB0 * fB0.y + wB1 * fB1.y + wB2 * fB2.y + wB3 * fB3.y;
        accB.z += wB0 * fB0.z + wB1 * fB1.z + wB2 * fB2.z + wB3 * fB3.z;
        accB.w += wB0 * fB0.w + wB1 * fB1.w + wB2 * fB2.w + wB3 * fB3.w;
        wsumA += (wA0 + wA1) + (wA2 + wA3);
        wsumB += (wB0 + wB1) + (wB2 + wB3);
    }
    for (; k < deg; k++) {
        int s0 = __ldg(&colsrc[start + k]);
        float4 l0 = __ldg((const float4*)(el + (size_t)s0 * 4));
        float4 fA0 = *(const float4*)(ftA + (size_t)s0 * 256);
        float4 fB0 = *(const float4*)(ftB + (size_t)s0 * 256);
        float wA0 = leaky_exp((hlo ? l0.x : l0.y) + erA);
        float wB0 = leaky_exp((hlo ? l0.z : l0.w) + erB);
        accA.x += wA0 * fA0.x; accA.y += wA0 * fA0.y;
        accA.z += wA0 * fA0.z; accA.w += wA0 * fA0.w;
        accB.x += wB0 * fB0.x; accB.y += wB0 * fB0.y;
        accB.z += wB0 * fB0.z; accB.w += wB0 * fB0.w;
        wsumA += wA0; wsumB += wB0;
    }

    float invA = (deg > 0) ? (1.f / wsumA) : 0.f;
    float invB = (deg > 0) ? (1.f / wsumB) : 0.f;
    float4 bA = __ldg((const float4*)(bias + lane * 4));
    float4 bB = __ldg((const float4*)(bias + 128 + lane * 4));
    float4 oA, oB;
    oA.x = fmaxf(accA.x * invA + bA.x, 0.f);
    oA.y = fmaxf(accA.y * invA + bA.y, 0.f);
    oA.z = fmaxf(accA.z * invA + bA.z, 0.f);
    oA.w = fmaxf(accA.w * invA + bA.w, 0.f);
    oB.x = fmaxf(accB.x * invB + bB.x, 0.f);
    oB.y = fmaxf(accB.y * invB + bB.y, 0.f);
    oB.z = fmaxf(accB.z * invB + bB.z, 0.f);
    oB.w = fmaxf(accB.w * invB + bB.w, 0.f);
    *(float4*)(out + (size_t)n * 256 + lane * 4) = oA;
    *(float4*)(out + (size_t)n * 256 + 128 + lane * 4) = oB;
}

// layer 2: H=1, D=128, fp32 features. el/er as two partial arrays [2][Nn].
__global__ __launch_bounds__(256) void aggregate2_kernel(
    const float* __restrict__ ft, const float* __restrict__ elp, const float* __restrict__ erp,
    const int* __restrict__ rowptr, const int* __restrict__ colsrc,
    const float* __restrict__ bias, float* __restrict__ out, int Nn)
{
    int warp = threadIdx.x >> 5, lane = threadIdx.x & 31;
    int n = blockIdx.x * 8 + warp;
    if (n >= Nn) return;
    int start = rowptr[n];
    int deg = rowptr[n + 1] - start;

    float er_n = __ldg(&erp[n]) + __ldg(&erp[Nn + n]);
    float4 acc = make_float4(0.f, 0.f, 0.f, 0.f);
    float wsum = 0.f;
    const float* ftp = ft + lane * 4;

    int k = 0;
    for (; k + 8 <= deg; k += 8) {
        int s[8];
        #pragma unroll
        for (int u = 0; u < 8; u++) s[u] = __ldg(&colsrc[start + k + u]);
        float e[8];
        #pragma unroll
        for (int u = 0; u < 8; u++) e[u] = __ldg(&elp[s[u]]) + __ldg(&elp[Nn + s[u]]);
        float4 f[8];
        #pragma unroll
        for (int u = 0; u < 8; u++) f[u] = *(const float4*)(ftp + (size_t)s[u] * 128);
        #pragma unroll
        for (int u = 0; u < 8; u++) {
            float w = leaky_exp(e[u] + er_n);
            acc.x += w * f[u].x; acc.y += w * f[u].y;
            acc.z += w * f[u].z; acc.w += w * f[u].w;
            wsum += w;
        }
    }
    for (; k < deg; k++) {
        int s0 = __ldg(&colsrc[start + k]);
        float w = leaky_exp(__ldg(&elp[s0]) + __ldg(&elp[Nn + s0]) + er_n);
        float4 f0 = *(const float4*)(ftp + (size_t)s0 * 128);
        acc.x += w * f0.x; acc.y += w * f0.y;
        acc.z += w * f0.z; acc.w += w * f0.w;
        wsum += w;
    }

    float inv = (deg > 0) ? (1.f / wsum) : 0.f;
    float4 b = __ldg((const float4*)(bias + lane * 4));
    float4 o;
    o.x = acc.x * inv + b.x;
    o.y = acc.y * inv + b.y;
    o.z = acc.z * inv + b.z;
    o.w = acc.w * inv + b.w;
    *(float4*)(out + (size_t)n * 128 + lane * 4) = o;
}

// ---------------- launch ----------------
extern "C" void kernel_launch(void* const* d_in, const int* in_sizes, int n_in,
                              void* d_out, int out_size)
{
    const float* feat    = (const float*)d_in[0];
    const int*   src     = (const int*)  d_in[1];
    const int*   dst     = (const int*)  d_in[2];
    const float* W1      = (const float*)d_in[3];
    const float* attn_l1 = (const float*)d_in[4];
    const float* attn_r1 = (const float*)d_in[5];
    const float* bias1   = (const float*)d_in[6];
    const float* W2      = (const float*)d_in[7];
    const float* attn_l2 = (const float*)d_in[8];
    const float* attn_r2 = (const float*)d_in[9];
    const float* bias2   = (const float*)d_in[10];
    float* out = (float*)d_out;

    float *ft1, *h1, *el1, *er1, *ft2, *el2p, *er2p;
    __half *wt1h, *wt1l, *wt2h, *wt2l;
    int *cnt, *rowptr, *colsrc;
    cudaGetSymbolAddress((void**)&ft1,    g_ft1);
    cudaGetSymbolAddress((void**)&h1,     g_h1);
    cudaGetSymbolAddress((void**)&el1,    g_el1);
    cudaGetSymbolAddress((void**)&er1,    g_er1);
    cudaGetSymbolAddress((void**)&ft2,    g_ft2);
    cudaGetSymbolAddress((void**)&el2p,   g_el2p);
    cudaGetSymbolAddress((void**)&er2p,   g_er2p);
    cudaGetSymbolAddress((void**)&wt1h,   g_wt1h);
    cudaGetSymbolAddress((void**)&wt1l,   g_wt1l);
    cudaGetSymbolAddress((void**)&wt2h,   g_wt2h);
    cudaGetSymbolAddress((void**)&wt2l,   g_wt2l);
    cudaGetSymbolAddress((void**)&cnt,    g_cnt);
    cudaGetSymbolAddress((void**)&rowptr, g_rowptr);
    cudaGetSymbolAddress((void**)&colsrc, g_colsrc);

    const int SMEM_SZ = (2 * 128 * 40) * 4 + (2 * 2 * 64 * 20) * 4 + 256 * 4;
    cudaFuncSetAttribute(mma_gemm_f16_kernel<4>, cudaFuncAttributeMaxDynamicSharedMemorySize, SMEM_SZ);
    cudaFuncSetAttribute(mma_gemm_f16_kernel<1>, cudaFuncAttributeMaxDynamicSharedMemorySize, SMEM_SZ);

    // side stream + events, created once on the first (uncaptured) call
    static cudaStream_t sB = [] {
        cudaStream_t s; cudaStreamCreateWithFlags(&s, cudaStreamNonBlocking); return s;
    }();
    static cudaEvent_t evFork = [] {
        cudaEvent_t e; cudaEventCreateWithFlags(&e, cudaEventDisableTiming); return e;
    }();
    static cudaEvent_t evCSR = [] {
        cudaEvent_t e; cudaEventCreateWithFlags(&e, cudaEventDisableTiming); return e;
    }();

    // fork: CSR build on side stream, GEMM path on main (default) stream
    cudaEventRecord(evFork, 0);
    cudaStreamWaitEvent(sB, evFork, 0);

    // side stream: CSR build (independent of gemm1)
    zero_int_kernel<<<256, 256, 0, sB>>>(cnt, N_NODES);
    count_dst_kernel<<<2048, 256, 0, sB>>>(dst, cnt, N_EDGES);
    scan_kernel<<<1, 1024, 0, sB>>>(cnt, rowptr, N_NODES);
    scatter_kernel<<<2048, 256, 0, sB>>>(src, dst, rowptr, cnt, colsrc, N_EDGES);
    cudaEventRecord(evCSR, sB);

    // main stream: weights prep + gemm1
    transpose_split_kernel<<<384, 256>>>(W1, W2, wt1h, wt1l, wt2h, wt2l);
    {
        dim3 grid(4, (N_NODES + 127) / 128);
        mma_gemm_f16_kernel<4><<<grid, 256, SMEM_SZ>>>(feat, wt1h, wt1l, ft1,
                                                       attn_l1, attn_r1, el1, er1,
                                                       N_NODES, 256);
    }

    // join: aggregation needs CSR + gemm1
    cudaStreamWaitEvent(0, evCSR, 0);
    aggregate1_kernel<<<(N_NODES + 7) / 8, 256>>>(ft1, el1, er1, rowptr, colsrc,
                                                  bias1, h1, N_NODES);
    {
        dim3 grid(2, (N_NODES + 127) / 128);
        mma_gemm_f16_kernel<1><<<grid, 256, SMEM_SZ>>>(h1, wt2h, wt2l, ft2,
                                                       attn_l2, attn_r2, el2p, er2p,
                                                       N_NODES, 128);
    }
    aggregate2_kernel<<<(N_NODES + 7) / 8, 256>>>(ft2, el2p, er2p, rowptr, colsrc,
                                                  bias2, out, N_NODES);
}

// round 11
// speedup vs baseline: 1.2491x; 1.2491x over previous
#include <cuda_runtime.h>
#include <cuda_fp16.h>
#include <math.h>
#include <stdint.h>

#define N_NODES 50000
#define N_EDGES 800000
#define NEG_SLOPE 0.2f

// ---------------- scratch (device globals; no allocation allowed) ----------------
__device__ float  g_ft1[N_NODES * 256];
__device__ float  g_h1 [N_NODES * 256];
__device__ float  g_el1[N_NODES * 4];
__device__ float  g_er1[N_NODES * 4];
__device__ float  g_ft2[N_NODES * 128];
__device__ float  g_el2p[2 * N_NODES];
__device__ float  g_er2p[2 * N_NODES];
__device__ int    g_cnt[N_NODES];
__device__ int    g_rowptr[N_NODES + 1];
__device__ int    g_colsrc[N_EDGES];
__device__ __half g_wt1h[256 * 256];   // W1^T hi fp16 [n][k]
__device__ __half g_wt1l[256 * 256];   // W1^T lo fp16
__device__ __half g_wt2h[128 * 256];   // W2^T hi
__device__ __half g_wt2l[128 * 256];   // W2^T lo

// ---------------- helpers ----------------
__device__ __forceinline__ uint32_t smem_u32(const void* p) {
    uint32_t a;
    asm("{ .reg .u64 t; cvta.to.shared.u64 t, %1; cvt.u32.u64 %0, t; }" : "=r"(a) : "l"(p));
    return a;
}

#define CP_ASYNC16(sa, gp) \
    asm volatile("cp.async.cg.shared.global [%0], [%1], 16;" :: "r"(sa), "l"(gp) : "memory")
#define CP_ASYNC16_Z(sa, gp, sz) \
    asm volatile("cp.async.cg.shared.global [%0], [%1], 16, %2;" :: "r"(sa), "l"(gp), "r"(sz) : "memory")
#define CP_COMMIT()  asm volatile("cp.async.commit_group;" ::: "memory")
#define CP_WAIT(n)   asm volatile("cp.async.wait_group %0;" :: "n"(n) : "memory")

#define MMA_F16(d, a0, a1, a2, a3, b0, b1)                                    \
    asm volatile("mma.sync.aligned.m16n8k16.row.col.f32.f16.f16.f32 "         \
                 "{%0,%1,%2,%3}, {%4,%5,%6,%7}, {%8,%9}, {%0,%1,%2,%3};"      \
                 : "+f"(d[0]), "+f"(d[1]), "+f"(d[2]), "+f"(d[3])             \
                 : "r"(a0), "r"(a1), "r"(a2), "r"(a3), "r"(b0), "r"(b1))

// split a float2 into packed fp16 hi + fp16 residual lo
__device__ __forceinline__ void split2(float2 x, uint32_t& h, uint32_t& l) {
    __half2 hh = __floats2half2_rn(x.x, x.y);
    float2 hf = __half22float2(hh);
    __half2 ll = __floats2half2_rn(x.x - hf.x, x.y - hf.y);
    h = *reinterpret_cast<uint32_t*>(&hh);
    l = *reinterpret_cast<uint32_t*>(&ll);
}

// ---------------- small utils ----------------
__global__ void count_dst_kernel(const int* __restrict__ dst, int* __restrict__ cnt, int E) {
    for (int e = blockIdx.x * blockDim.x + threadIdx.x; e < E; e += gridDim.x * blockDim.x)
        atomicAdd(&cnt[dst[e]], 1);
}

// transpose + fp16 hi/lo split of both weight matrices; also zeroes cnt[]
__global__ void transpose_split_kernel(const float* __restrict__ W1, const float* __restrict__ W2,
                                       __half* __restrict__ t1h, __half* __restrict__ t1l,
                                       __half* __restrict__ t2h, __half* __restrict__ t2l,
                                       int* __restrict__ cnt) {
    int t = blockIdx.x * blockDim.x + threadIdx.x;
    if (t < N_NODES) cnt[t] = 0;
    if (t < 65536) {
        int k = t & 255, n = t >> 8;
        float v = W1[k * 256 + n];
        __half h = __float2half_rn(v);
        t1h[n * 256 + k] = h;
        t1l[n * 256 + k] = __float2half_rn(v - __half2float(h));
    } else if (t < 98304) {
        int u = t - 65536;
        int k = u & 255, n = u >> 8;
        float v = W2[k * 128 + n];
        __half h = __float2half_rn(v);
        t2h[n * 256 + k] = h;
        t2l[n * 256 + k] = __float2half_rn(v - __half2float(h));
    }
}

// single-block exclusive scan
__global__ void scan_kernel(const int* __restrict__ cnt, int* __restrict__ rowptr, int n) {
    __shared__ int warp_sums[32];
    __shared__ int s_carry;
    int tid = threadIdx.x;
    if (tid == 0) { s_carry = 0; rowptr[0] = 0; }
    __syncthreads();
    for (int base = 0; base < n; base += 1024) {
        int idx = base + tid;
        int v = (idx < n) ? cnt[idx] : 0;
        int lane = tid & 31, warp = tid >> 5;
        int x = v;
        #pragma unroll
        for (int off = 1; off < 32; off <<= 1) {
            int y = __shfl_up_sync(0xffffffffu, x, off);
            if (lane >= off) x += y;
        }
        if (lane == 31) warp_sums[warp] = x;
        __syncthreads();
        if (warp == 0) {
            int s = warp_sums[lane];
            #pragma unroll
            for (int off = 1; off < 32; off <<= 1) {
                int y = __shfl_up_sync(0xffffffffu, s, off);
                if (lane >= off) s += y;
            }
            warp_sums[lane] = s;
        }
        __syncthreads();
        int warp_off = (warp > 0) ? warp_sums[warp - 1] : 0;
        int incl = x + warp_off + s_carry;
        if (idx < n) rowptr[idx + 1] = incl;
        __syncthreads();
        if (tid == 1023) s_carry = incl;
        __syncthreads();
    }
}

__global__ void scatter_kernel(const int* __restrict__ src, const int* __restrict__ dst,
                               const int* __restrict__ rowptr, int* __restrict__ cnt,
                               int* __restrict__ colsrc, int E) {
    for (int e = blockIdx.x * blockDim.x + threadIdx.x; e < E; e += gridDim.x * blockDim.x) {
        int d = dst[e];
        int pos = atomicSub(&cnt[d], 1);
        colsrc[rowptr[d] + pos - 1] = src[e];
    }
}

// ---------------- fp16 split-MMA GEMM (cp.async double-buffered) + fused el/er ----------------
// 8x1 warp grid: warp owns 16 full rows (16x64 warp tile). A split once per element;
// el/er dot completes with a q-shuffle (no cross-warp smem exchange).
template <int HEADS>
__global__ __launch_bounds__(256, 3) void mma_gemm_f16_kernel(
    const float* __restrict__ A,
    const __half* __restrict__ Bth, const __half* __restrict__ Btl,
    float* __restrict__ C,
    const float* __restrict__ attn_l, const float* __restrict__ attn_r,
    float* __restrict__ el, float* __restrict__ er,
    int M, int Nc)
{
    const int BM = 128, BN = 64, BK = 32, K = 256;
    const int ASTR = 40;    // f32 per A row
    const int BSTR2 = 20;   // half2 per B row
    extern __shared__ float sm[];
    float*   As  = sm;                                    // [2][BM][40] f32
    __half2* Bh2 = (__half2*)(As + 2 * BM * ASTR);        // [2][BN][20] half2 hi
    __half2* Bl2 = Bh2 + 2 * BN * BSTR2;                  // [2][BN][20] half2 lo

    uint32_t as_b = smem_u32(As);
    uint32_t bh_b = smem_u32(Bh2);
    uint32_t bl_b = smem_u32(Bl2);

    int tid = threadIdx.x, lane = tid & 31, warp = tid >> 5;
    int blockRow = blockIdx.y * BM;
    int blockCol = blockIdx.x * BN;
    int g = lane >> 2, q = lane & 3;

    float acc[8][4];
    #pragma unroll
    for (int j = 0; j < 8; j++)
        #pragma unroll
        for (int c = 0; c < 4; c++) acc[j][c] = 0.f;

    auto load_tile = [&](int t) {
        int buf = t & 1, k0 = t * BK;
        #pragma unroll
        for (int l = 0; l < 4; l++) {
            int c = tid + l * 256;
            int r = c >> 3, kq = (c & 7) * 4;
            const float* gp = A + (size_t)(blockRow + r) * K + k0 + kq;
            uint32_t sa = as_b + (uint32_t)(((buf * BM + r) * ASTR + kq) * 4);
            uint32_t sz = (blockRow + r < M) ? 16u : 0u;
            CP_ASYNC16_Z(sa, gp, sz);
        }
        {
            int n = tid >> 2, ch = tid & 3;
            size_t go = (size_t)(blockCol + n) * K + k0 + ch * 8;
            uint32_t so = (uint32_t)(((buf * BN + n) * BSTR2 + ch * 4) * 4);
            CP_ASYNC16(bh_b + so, Bth + go);
            CP_ASYNC16(bl_b + so, Btl + go);
        }
        CP_COMMIT();
    };

    load_tile(0);

    #pragma unroll 1
    for (int t = 0; t < K / BK; t++) {
        if (t < K / BK - 1) {
            load_tile(t + 1);
            CP_WAIT(1);
        } else {
            CP_WAIT(0);
        }
        __syncthreads();

        int buf = t & 1;
        const float2*  Af2 = (const float2*)(As + buf * BM * ASTR);
        const __half2* Bhb = Bh2 + buf * BN * BSTR2;
        const __half2* Blb = Bl2 + buf * BN * BSTR2;

        #pragma unroll
        for (int ks = 0; ks < 2; ks++) {
            int kof = ks * 8;
            int r0 = warp * 16 + g;
            // A fragments (rows r0, r0+8; k-pairs q, q+4), split once per element
            uint32_t ah[4], al[4];
            float2 x00 = Af2[(r0    ) * 20 + kof + q];
            float2 x10 = Af2[(r0 + 8) * 20 + kof + q];
            float2 x01 = Af2[(r0    ) * 20 + kof + q + 4];
            float2 x11 = Af2[(r0 + 8) * 20 + kof + q + 4];
            split2(x00, ah[0], al[0]);
            split2(x10, ah[1], al[1]);
            split2(x01, ah[2], al[2]);
            split2(x11, ah[3], al[3]);
            #pragma unroll
            for (int j = 0; j < 8; j++) {
                int nb = j * 8 + g;
                uint32_t b0h = *reinterpret_cast<const uint32_t*>(&Bhb[nb * BSTR2 + kof + q]);
                uint32_t b1h = *reinterpret_cast<const uint32_t*>(&Bhb[nb * BSTR2 + kof + q + 4]);
                uint32_t b0l = *reinterpret_cast<const uint32_t*>(&Blb[nb * BSTR2 + kof + q]);
                uint32_t b1l = *reinterpret_cast<const uint32_t*>(&Blb[nb * BSTR2 + kof + q + 4]);
                MMA_F16(acc[j], ah[0], ah[1], ah[2], ah[3], b0h, b1h);
                MMA_F16(acc[j], al[0], al[1], al[2], al[3], b0h, b1h);
                MMA_F16(acc[j], ah[0], ah[1], ah[2], ah[3], b0l, b1l);
            }
        }
        __syncthreads();
    }

    // ---- store C (fp32) ----
    int r0 = blockRow + warp * 16 + g;
    int r1 = r0 + 8;
    #pragma unroll
    for (int j = 0; j < 8; j++) {
        int c = blockCol + j * 8 + q * 2;
        if (r0 < M) *(float2*)(C + (size_t)r0 * Nc + c) = make_float2(acc[j][0], acc[j][1]);
        if (r1 < M) *(float2*)(C + (size_t)r1 * Nc + c) = make_float2(acc[j][2], acc[j][3]);
    }

    // ---- fused el/er epilogue: whole row in one warp -> q-shuffle completes dot ----
    float pl0 = 0.f, pl1 = 0.f, pr0 = 0.f, pr1 = 0.f;
    #pragma unroll
    for (int j = 0; j < 8; j++) {
        int idx = blockCol + j * 8 + q * 2;
        float a0 = __ldg(&attn_l[idx]), a1 = __ldg(&attn_l[idx + 1]);
        float b0 = __ldg(&attn_r[idx]), b1 = __ldg(&attn_r[idx + 1]);
        pl0 += acc[j][0] * a0 + acc[j][1] * a1;
        pl1 += acc[j][2] * a0 + acc[j][3] * a1;
        pr0 += acc[j][0] * b0 + acc[j][1] * b1;
        pr1 += acc[j][2] * b0 + acc[j][3] * b1;
    }
    #pragma unroll
    for (int off = 1; off <= 2; off <<= 1) {
        pl0 += __shfl_xor_sync(0xffffffffu, pl0, off);
        pl1 += __shfl_xor_sync(0xffffffffu, pl1, off);
        pr0 += __shfl_xor_sync(0xffffffffu, pr0, off);
        pr1 += __shfl_xor_sync(0xffffffffu, pr1, off);
    }
    if (q == 0) {
        if (r0 < M) {
            if (HEADS == 1) {
                el[(size_t)blockIdx.x * M + r0] = pl0;
                er[(size_t)blockIdx.x * M + r0] = pr0;
            } else {
                el[(size_t)r0 * HEADS + blockIdx.x] = pl0;
                er[(size_t)r0 * HEADS + blockIdx.x] = pr0;
            }
        }
        if (r1 < M) {
            if (HEADS == 1) {
                el[(size_t)blockIdx.x * M + r1] = pl1;
                er[(size_t)blockIdx.x * M + r1] = pr1;
            } else {
                el[(size_t)r1 * HEADS + blockIdx.x] = pl1;
                er[(size_t)r1 * HEADS + blockIdx.x] = pr1;
            }
        }
    }
}

// ---------------- fused softmax + aggregation ----------------
__device__ __forceinline__ float leaky_exp(float e) {
    e = (e > 0.f) ? e : NEG_SLOPE * e;
    return __expf(e);
}

// layer 1: H=4, D=64, C=256, fp32 features. One warp per node.
__global__ __launch_bounds__(256) void aggregate1_kernel(
    const float* __restrict__ ft, const float* __restrict__ el, const float* __restrict__ er,
    const int* __restrict__ rowptr, const int* __restrict__ colsrc,
    const float* __restrict__ bias, float* __restrict__ out, int Nn)
{
    int warp = threadIdx.x >> 5, lane = threadIdx.x & 31;
    int n = blockIdx.x * 8 + warp;
    if (n >= Nn) return;
    int start = rowptr[n];
    int deg = rowptr[n + 1] - start;

    const bool hlo = (lane < 16);
    float4 er4 = __ldg((const float4*)(er + (size_t)n * 4));
    float erA = hlo ? er4.x : er4.y;
    float erB = hlo ? er4.z : er4.w;

    float4 accA = make_float4(0.f, 0.f, 0.f, 0.f);
    float4 accB = make_float4(0.f, 0.f, 0.f, 0.f);
    float wsumA = 0.f, wsumB = 0.f;
    const float* ftA = ft + lane * 4;
    const float* ftB = ft + 128 + lane * 4;

    int k = 0;
    for (; k + 4 <= deg; k += 4) {
        int s0 = __ldg(&colsrc[start + k + 0]);
        int s1 = __ldg(&colsrc[start + k + 1]);
        int s2 = __ldg(&colsrc[start + k + 2]);
        int s3 = __ldg(&colsrc[start + k + 3]);
        float4 l0 = __ldg((const float4*)(el + (size_t)s0 * 4));
        float4 l1 = __ldg((const float4*)(el + (size_t)s1 * 4));
        float4 l2 = __ldg((const float4*)(el + (size_t)s2 * 4));
        float4 l3 = __ldg((const float4*)(el + (size_t)s3 * 4));
        float4 fA0 = *(const float4*)(ftA + (size_t)s0 * 256);
        float4 fB0 = *(const float4*)(ftB + (size_t)s0 * 256);
        float4 fA1 = *(const float4*)(ftA + (size_t)s1 * 256);
        float4 fB1 = *(const float4*)(ftB + (size_t)s1 * 256);
        float4 fA2 = *(const float4*)(ftA + (size_t)s2 * 256);
        float4 fB2 = *(const float4*)(ftB + (size_t)s2 * 256);
        float4 fA3 = *(const float4*)(ftA + (size_t)s3 * 256);
        float4 fB3 = *(const float4*)(ftB + (size_t)s3 * 256);
        float wA0 = leaky_exp((hlo ? l0.x : l0.y) + erA);
        float wB0 = leaky_exp((hlo ? l0.z : l0.w) + erB);
        float wA1 = leaky_exp((hlo ? l1.x : l1.y) + erA);
        float wB1 = leaky_exp((hlo ? l1.z : l1.w) + erB);
        float wA2 = leaky_exp((hlo ? l2.x : l2.y) + erA);
        float wB2 = leaky_exp((hlo ? l2.z : l2.w) + erB);
        float wA3 = leaky_exp((hlo ? l3.x : l3.y) + erA);
        float wB3 = leaky_exp((hlo ? l3.z : l3.w) + erB);
        accA.x += wA0 * fA0.x + wA1 * fA1.x + wA2 * fA2.x + wA3 * fA3.x;
        accA.y += wA0 * fA0.y + wA1 * fA1.y + wA2 * fA2.y + wA3 * fA3.y;
        accA.z += wA0 * fA0.z + wA1 * fA1.z + wA2 * fA2.z + wA3 * fA3.z;
        accA.w += wA0 * fA0.w + wA1 * fA1.w + wA2 * fA2.w + wA3 * fA3.w;
        accB.x += wB0 * fB0.x + wB1 * fB1.x + wB2 * fB2.x + wB3 * fB3.x;
        accB.y += wB0 * fB0.y + wB1 * fB1.y + wB2 * fB2.y + wB3 * fB3.y;
        accB.z += wB0 * fB0.z + wB1 * fB1.z + wB2 * fB2.z + wB3 * fB3.z;
        accB.w += wB0 * fB0.w + wB1 * fB1.w + wB2 * fB2.w + wB3 * fB3.w;
        wsumA += (wA0 + wA1) + (wA2 + wA3);
        wsumB += (wB0 + wB1) + (wB2 + wB3);
    }
    for (; k < deg; k++) {
        int s0 = __ldg(&colsrc[start + k]);
        float4 l0 = __ldg((const float4*)(el + (size_t)s0 * 4));
        float4 fA0 = *(const float4*)(ftA + (size_t)s0 * 256);
        float4 fB0 = *(const float4*)(ftB + (size_t)s0 * 256);
        float wA0 = leaky_exp((hlo ? l0.x : l0.y) + erA);
        float wB0 = leaky_exp((hlo ? l0.z : l0.w) + erB);
        accA.x += wA0 * fA0.x; accA.y += wA0 * fA0.y;
        accA.z += wA0 * fA0.z; accA.w += wA0 * fA0.w;
        accB.x += wB0 * fB0.x; accB.y += wB0 * fB0.y;
        accB.z += wB0 * fB0.z; accB.w += wB0 * fB0.w;
        wsumA += wA0; wsumB += wB0;
    }

    float invA = (deg > 0) ? (1.f / wsumA) : 0.f;
    float invB = (deg > 0) ? (1.f / wsumB) : 0.f;
    float4 bA = __ldg((const float4*)(bias + lane * 4));
    float4 bB = __ldg((const float4*)(bias + 128 + lane * 4));
    float4 oA, oB;
    oA.x = fmaxf(accA.x * invA + bA.x, 0.f);
    oA.y = fmaxf(accA.y * invA + bA.y, 0.f);
    oA.z = fmaxf(accA.z * invA + bA.z, 0.f);
    oA.w = fmaxf(accA.w * invA + bA.w, 0.f);
    oB.x = fmaxf(accB.x * invB + bB.x, 0.f);
    oB.y = fmaxf(accB.y * invB + bB.y, 0.f);
    oB.z = fmaxf(accB.z * invB + bB.z, 0.f);
    oB.w = fmaxf(accB.w * invB + bB.w, 0.f);
    *(float4*)(out + (size_t)n * 256 + lane * 4) = oA;
    *(float4*)(out + (size_t)n * 256 + 128 + lane * 4) = oB;
}

// layer 2: H=1, D=128, fp32 features. el/er as two partial arrays [2][Nn].
__global__ __launch_bounds__(256) void aggregate2_kernel(
    const float* __restrict__ ft, const float* __restrict__ elp, const float* __restrict__ erp,
    const int* __restrict__ rowptr, const int* __restrict__ colsrc,
    const float* __restrict__ bias, float* __restrict__ out, int Nn)
{
    int warp = threadIdx.x >> 5, lane = threadIdx.x & 31;
    int n = blockIdx.x * 8 + warp;
    if (n >= Nn) return;
    int start = rowptr[n];
    int deg = rowptr[n + 1] - start;

    float er_n = __ldg(&erp[n]) + __ldg(&erp[Nn + n]);
    float4 acc = make_float4(0.f, 0.f, 0.f, 0.f);
    float wsum = 0.f;
    const float* ftp = ft + lane * 4;

    int k = 0;
    for (; k + 8 <= deg; k += 8) {
        int s[8];
        #pragma unroll
        for (int u = 0; u < 8; u++) s[u] = __ldg(&colsrc[start + k + u]);
        float e[8];
        #pragma unroll
        for (int u = 0; u < 8; u++) e[u] = __ldg(&elp[s[u]]) + __ldg(&elp[Nn + s[u]]);
        float4 f[8];
        #pragma unroll
        for (int u = 0; u < 8; u++) f[u] = *(const float4*)(ftp + (size_t)s[u] * 128);
        #pragma unroll
        for (int u = 0; u < 8; u++) {
            float w = leaky_exp(e[u] + er_n);
            acc.x += w * f[u].x; acc.y += w * f[u].y;
            acc.z += w * f[u].z; acc.w += w * f[u].w;
            wsum += w;
        }
    }
    for (; k < deg; k++) {
        int s0 = __ldg(&colsrc[start + k]);
        float w = leaky_exp(__ldg(&elp[s0]) + __ldg(&elp[Nn + s0]) + er_n);
        float4 f0 = *(const float4*)(ftp + (size_t)s0 * 128);
        acc.x += w * f0.x; acc.y += w * f0.y;
        acc.z += w * f0.z; acc.w += w * f0.w;
        wsum += w;
    }

    float inv = (deg > 0) ? (1.f / wsum) : 0.f;
    float4 b = __ldg((const float4*)(bias + lane * 4));
    float4 o;
    o.x = acc.x * inv + b.x;
    o.y = acc.y * inv + b.y;
    o.z = acc.z * inv + b.z;
    o.w = acc.w * inv + b.w;
    *(float4*)(out + (size_t)n * 128 + lane * 4) = o;
}

// ---------------- launch (single stream) ----------------
extern "C" void kernel_launch(void* const* d_in, const int* in_sizes, int n_in,
                              void* d_out, int out_size)
{
    const float* feat    = (const float*)d_in[0];
    const int*   src     = (const int*)  d_in[1];
    const int*   dst     = (const int*)  d_in[2];
    const float* W1      = (const float*)d_in[3];
    const float* attn_l1 = (const float*)d_in[4];
    const float* attn_r1 = (const float*)d_in[5];
    const float* bias1   = (const float*)d_in[6];
    const float* W2      = (const float*)d_in[7];
    const float* attn_l2 = (const float*)d_in[8];
    const float* attn_r2 = (const float*)d_in[9];
    const float* bias2   = (const float*)d_in[10];
    float* out = (float*)d_out;

    float *ft1, *h1, *el1, *er1, *ft2, *el2p, *er2p;
    __half *wt1h, *wt1l, *wt2h, *wt2l;
    int *cnt, *rowptr, *colsrc;
    cudaGetSymbolAddress((void**)&ft1,    g_ft1);
    cudaGetSymbolAddress((void**)&h1,     g_h1);
    cudaGetSymbolAddress((void**)&el1,    g_el1);
    cudaGetSymbolAddress((void**)&er1,    g_er1);
    cudaGetSymbolAddress((void**)&ft2,    g_ft2);
    cudaGetSymbolAddress((void**)&el2p,   g_el2p);
    cudaGetSymbolAddress((void**)&er2p,   g_er2p);
    cudaGetSymbolAddress((void**)&wt1h,   g_wt1h);
    cudaGetSymbolAddress((void**)&wt1l,   g_wt1l);
    cudaGetSymbolAddress((void**)&wt2h,   g_wt2h);
    cudaGetSymbolAddress((void**)&wt2l,   g_wt2l);
    cudaGetSymbolAddress((void**)&cnt,    g_cnt);
    cudaGetSymbolAddress((void**)&rowptr, g_rowptr);
    cudaGetSymbolAddress((void**)&colsrc, g_colsrc);

    const int SMEM_SZ = (2 * 128 * 40) * 4 + (2 * 2 * 64 * 20) * 4;
    cudaFuncSetAttribute(mma_gemm_f16_kernel<4>, cudaFuncAttributeMaxDynamicSharedMemorySize, SMEM_SZ);
    cudaFuncSetAttribute(mma_gemm_f16_kernel<1>, cudaFuncAttributeMaxDynamicSharedMemorySize, SMEM_SZ);

    transpose_split_kernel<<<384, 256>>>(W1, W2, wt1h, wt1l, wt2h, wt2l, cnt);     // 1 (+ zero cnt)
    count_dst_kernel<<<2048, 256>>>(dst, cnt, N_EDGES);                            // 2
    scan_kernel<<<1, 1024>>>(cnt, rowptr, N_NODES);                                // 3
    {                                                                              // 4: gemm1 (profiled)
        dim3 grid(4, (N_NODES + 127) / 128);
        mma_gemm_f16_kernel<4><<<grid, 256, SMEM_SZ>>>(feat, wt1h, wt1l, ft1,
                                                       attn_l1, attn_r1, el1, er1,
                                                       N_NODES, 256);
    }
    scatter_kernel<<<2048, 256>>>(src, dst, rowptr, cnt, colsrc, N_EDGES);         // 5
    aggregate1_kernel<<<(N_NODES + 7) / 8, 256>>>(ft1, el1, er1, rowptr, colsrc,   // 6
                                                  bias1, h1, N_NODES);
    {                                                                              // 7: gemm2
        dim3 grid(2, (N_NODES + 127) / 128);
        mma_gemm_f16_kernel<1><<<grid, 256, SMEM_SZ>>>(h1, wt2h, wt2l, ft2,
                                                       attn_l2, attn_r2, el2p, er2p,
                                                       N_NODES, 128);
    }
    aggregate2_kernel<<<(N_NODES + 7) / 8, 256>>>(ft2, el2p, er2p, rowptr, colsrc, // 8
                                                  bias2, out, N_NODES);
}